// round 14
// baseline (speedup 1.0000x reference)
#include <cuda_runtime.h>
#include <cuda_bf16.h>
#include <cstddef>

// ---------------------------------------------------------------------------
// DCT_61340722921773 — round 14
//
// Per contiguous 64-float patch (8x8 X): Y = C^T X C, basis as immediates.
//
// Cost-model finding (R13 post-mortem): all layout families cost ~14 L1-pipe
// cyc/patch (dense loads are exactly offset by exchange shuffles) — traffic
// shaping is exhausted. Profile (L1 69 / DRAM 64 / issue 64 / occ 83) says
// LATENCY-bound: the serial 6-step shfl butterfly chain (~200cyc) dominates.
//
// This round: 4 patches per thread (q + m*quarter, m=0..3) so warp address
// patterns are unchanged; butterflies interleaved 4-wide (16 independent
// shfls per step), 8 front-batched streaming LDG.128 (MLP=8/thread).
// Critical path per patch halves vs R13.
// ---------------------------------------------------------------------------

#define CA 0.35355339059327373f   // sqrt(1/8)
#define C1 0.4903926402016152f
#define C2 0.46193976625564337f
#define C3 0.4157348061512726f
#define C4 0.35355339059327373f
#define C5 0.2777851165098011f
#define C6 0.1913417161825449f
#define C7 0.09754516100806412f

// Cmat[u][i] = s(u) * cos((2i+1)*u*pi/16)
__device__ constexpr float Cmat[8][8] = {
    {  CA,  CA,  CA,  CA,  CA,  CA,  CA,  CA },
    {  C1,  C3,  C5,  C7, -C7, -C5, -C3, -C1 },
    {  C2,  C6, -C6, -C2, -C2, -C6,  C6,  C2 },
    {  C3, -C7, -C1, -C5,  C5,  C1,  C7, -C3 },
    {  C4, -C4, -C4,  C4,  C4, -C4, -C4,  C4 },
    {  C5, -C1,  C7,  C3, -C3, -C7,  C1, -C5 },
    {  C6, -C2,  C2, -C6, -C6,  C2, -C2,  C6 },
    {  C7, -C5,  C3, -C1,  C1, -C3,  C5, -C7 },
};

// Quad 8x8 transpose among 8 lanes, four arrays interleaved per butterfly
// step: 16 independent shfls per step hide the ~26-cyc shfl latency.
__device__ __forceinline__ void transpose8_quad(float v[4][8], int g)
{
#pragma unroll
    for (int d = 1; d < 8; d <<= 1) {
        const bool hi = (g & d) != 0;
#pragma unroll
        for (int s0 = 0; s0 < 8; ++s0) {
            if (s0 & d) continue;            // pair (s0, s0|d)
            const int s1 = s0 | d;
#pragma unroll
            for (int m = 0; m < 4; ++m) {
                float send = hi ? v[m][s0] : v[m][s1];
                float recv = __shfl_xor_sync(0xffffffffu, send, d);
                if (hi) v[m][s0] = recv; else v[m][s1] = recv;
            }
        }
    }
}

// 8-point DCT with even/odd parity folding:
// out[j] = E[j] + O[j], out[7-j] = E[j] - O[j]  (j = 0..3)
__device__ __forceinline__ void dct8(const float x[8], float out[8])
{
#pragma unroll
    for (int j = 0; j < 4; ++j) {
        float E = x[0] * Cmat[0][j];
        E = fmaf(x[2], Cmat[2][j], E);
        E = fmaf(x[4], Cmat[4][j], E);
        E = fmaf(x[6], Cmat[6][j], E);
        float O = x[1] * Cmat[1][j];
        O = fmaf(x[3], Cmat[3][j], O);
        O = fmaf(x[5], Cmat[5][j], O);
        O = fmaf(x[7], Cmat[7][j], O);
        out[j]     = E + O;
        out[7 - j] = E - O;
    }
}

constexpr int THREADS = 256;

__global__ void __launch_bounds__(THREADS)
dct14_kernel(const float4* __restrict__ in, float4* __restrict__ out,
             int quarter)          // quarter = npatch / 4
{
    const int tid = blockIdx.x * THREADS + threadIdx.x;
    const int g   = tid & 7;
    const int q   = tid >> 3;
    if (q >= quarter) return;      // exact grid; groups never split

    size_t f[4];
#pragma unroll
    for (int m = 0; m < 4; ++m)
        f[m] = (size_t)(q + m * quarter) * 16 + g * 2;

    // Front-batched loads: 8 independent streaming LDG.128.
    float4 lo[4], hi4[4];
#pragma unroll
    for (int m = 0; m < 4; ++m) lo[m]  = __ldcs(in + f[m]);
#pragma unroll
    for (int m = 0; m < 4; ++m) hi4[m] = __ldcs(in + f[m] + 1);

    float T[4][8];
    {
        // Stage 1 (rows): consume loads, produce T.
#pragma unroll
        for (int m = 0; m < 4; ++m) {
            float x[8] = { lo[m].x,  lo[m].y,  lo[m].z,  lo[m].w,
                           hi4[m].x, hi4[m].y, hi4[m].z, hi4[m].w };
            dct8(x, T[m]);
        }
    }

    transpose8_quad(T, g);

    float Y[4][8];
#pragma unroll
    for (int m = 0; m < 4; ++m)
        dct8(T[m], Y[m]);

    transpose8_quad(Y, g);

#pragma unroll
    for (int m = 0; m < 4; ++m) {
        __stcs(out + f[m],
               make_float4(Y[m][0], Y[m][1], Y[m][2], Y[m][3]));
        __stcs(out + f[m] + 1,
               make_float4(Y[m][4], Y[m][5], Y[m][6], Y[m][7]));
    }
}

extern "C" void kernel_launch(void* const* d_in, const int* in_sizes, int n_in,
                              void* d_out, int out_size)
{
    // d_in[0]: inputs, float32, (8,3,1024,1024); d_in[1]: 64x64 DCT matrix
    // (unused — basis baked in as immediates, identical formula).
    const float4* in  = (const float4*)d_in[0];
    float4*       out = (float4*)d_out;

    int npatch  = in_sizes[0] / 64;                  // 393216
    int quarter = npatch / 4;                        // 98304
    int nthread = quarter * 8;                       // 786432
    int blocks  = (nthread + THREADS - 1) / THREADS; // 3072 (exact)

    dct14_kernel<<<blocks, THREADS>>>(in, out, quarter);
}

// round 15
// speedup vs baseline: 1.0063x; 1.0063x over previous
#include <cuda_runtime.h>
#include <cuda_bf16.h>
#include <cstddef>

// ---------------------------------------------------------------------------
// DCT_61340722921773 — round 15
//
// Per contiguous 64-float patch (8x8 X): Y = C^T X C, basis as immediates.
//
// Model: MIO events ~14/patch (~19.6us) + DRAM floor ~25.5us; at R13 (2
// patches/thread, 29.0us) nothing saturated -> exposed latency. R14 showed
// 4 patches/thread kills occupancy (52 regs -> 42%). This round: 3 patches
// per thread — chain/patch = 2/3 of R13, ~44 regs -> ~70% occ.
//   * 6 front-batched streaming LDG.128 (MLP 6)
//   * butterflies interleaved 3-wide (12 independent shfls/step)
//   * patches at q, q+third, q+2*third: warp-level address pattern unchanged
// ---------------------------------------------------------------------------

#define CA 0.35355339059327373f   // sqrt(1/8)
#define C1 0.4903926402016152f
#define C2 0.46193976625564337f
#define C3 0.4157348061512726f
#define C4 0.35355339059327373f
#define C5 0.2777851165098011f
#define C6 0.1913417161825449f
#define C7 0.09754516100806412f

// Cmat[u][i] = s(u) * cos((2i+1)*u*pi/16)
__device__ constexpr float Cmat[8][8] = {
    {  CA,  CA,  CA,  CA,  CA,  CA,  CA,  CA },
    {  C1,  C3,  C5,  C7, -C7, -C5, -C3, -C1 },
    {  C2,  C6, -C6, -C2, -C2, -C6,  C6,  C2 },
    {  C3, -C7, -C1, -C5,  C5,  C1,  C7, -C3 },
    {  C4, -C4, -C4,  C4,  C4, -C4, -C4,  C4 },
    {  C5, -C1,  C7,  C3, -C3, -C7,  C1, -C5 },
    {  C6, -C2,  C2, -C6, -C6,  C2, -C2,  C6 },
    {  C7, -C5,  C3, -C1,  C1, -C3,  C5, -C7 },
};

// Triple 8x8 transpose among 8 lanes, three arrays interleaved per butterfly
// step: 12 independent shfls per step hide the ~26-cyc shfl latency.
__device__ __forceinline__ void transpose8_tri(float a[8], float b[8],
                                               float c[8], int g)
{
#pragma unroll
    for (int d = 1; d < 8; d <<= 1) {
        const bool hi = (g & d) != 0;
#pragma unroll
        for (int s0 = 0; s0 < 8; ++s0) {
            if (s0 & d) continue;            // pair (s0, s0|d)
            const int s1 = s0 | d;
            float sa = hi ? a[s0] : a[s1];
            float sb = hi ? b[s0] : b[s1];
            float sc = hi ? c[s0] : c[s1];
            float ra = __shfl_xor_sync(0xffffffffu, sa, d);
            float rb = __shfl_xor_sync(0xffffffffu, sb, d);
            float rc = __shfl_xor_sync(0xffffffffu, sc, d);
            if (hi) { a[s0] = ra; b[s0] = rb; c[s0] = rc; }
            else    { a[s1] = ra; b[s1] = rb; c[s1] = rc; }
        }
    }
}

// 8-point DCT with even/odd parity folding:
// out[j] = E[j] + O[j], out[7-j] = E[j] - O[j]  (j = 0..3)
__device__ __forceinline__ void dct8(const float x[8], float out[8])
{
#pragma unroll
    for (int j = 0; j < 4; ++j) {
        float E = x[0] * Cmat[0][j];
        E = fmaf(x[2], Cmat[2][j], E);
        E = fmaf(x[4], Cmat[4][j], E);
        E = fmaf(x[6], Cmat[6][j], E);
        float O = x[1] * Cmat[1][j];
        O = fmaf(x[3], Cmat[3][j], O);
        O = fmaf(x[5], Cmat[5][j], O);
        O = fmaf(x[7], Cmat[7][j], O);
        out[j]     = E + O;
        out[7 - j] = E - O;
    }
}

constexpr int THREADS = 256;

__global__ void __launch_bounds__(THREADS)
dct15_kernel(const float4* __restrict__ in, float4* __restrict__ out,
             int third)            // third = npatch / 3
{
    const int tid = blockIdx.x * THREADS + threadIdx.x;
    const int g   = tid & 7;
    const int q   = tid >> 3;
    if (q >= third) return;        // exact grid; groups never split

    const size_t f0 = (size_t)q * 16 + g * 2;
    const size_t f1 = (size_t)(q + third) * 16 + g * 2;
    const size_t f2 = (size_t)(q + 2 * third) * 16 + g * 2;

    // Front-batched loads: 6 independent streaming LDG.128.
    float4 a0 = __ldcs(in + f0);
    float4 b0 = __ldcs(in + f1);
    float4 c0 = __ldcs(in + f2);
    float4 a1 = __ldcs(in + f0 + 1);
    float4 b1 = __ldcs(in + f1 + 1);
    float4 c1 = __ldcs(in + f2 + 1);

    float tA[8], tB[8], tC[8];
    {
        float x[8] = { a0.x, a0.y, a0.z, a0.w, a1.x, a1.y, a1.z, a1.w };
        dct8(x, tA);
    }
    {
        float x[8] = { b0.x, b0.y, b0.z, b0.w, b1.x, b1.y, b1.z, b1.w };
        dct8(x, tB);
    }
    {
        float x[8] = { c0.x, c0.y, c0.z, c0.w, c1.x, c1.y, c1.z, c1.w };
        dct8(x, tC);
    }

    transpose8_tri(tA, tB, tC, g);

    float yA[8], yB[8], yC[8];
    dct8(tA, yA);
    dct8(tB, yB);
    dct8(tC, yC);

    transpose8_tri(yA, yB, yC, g);

    __stcs(out + f0,     make_float4(yA[0], yA[1], yA[2], yA[3]));
    __stcs(out + f0 + 1, make_float4(yA[4], yA[5], yA[6], yA[7]));
    __stcs(out + f1,     make_float4(yB[0], yB[1], yB[2], yB[3]));
    __stcs(out + f1 + 1, make_float4(yB[4], yB[5], yB[6], yB[7]));
    __stcs(out + f2,     make_float4(yC[0], yC[1], yC[2], yC[3]));
    __stcs(out + f2 + 1, make_float4(yC[4], yC[5], yC[6], yC[7]));
}

extern "C" void kernel_launch(void* const* d_in, const int* in_sizes, int n_in,
                              void* d_out, int out_size)
{
    // d_in[0]: inputs, float32, (8,3,1024,1024); d_in[1]: 64x64 DCT matrix
    // (unused — basis baked in as immediates, identical formula).
    const float4* in  = (const float4*)d_in[0];
    float4*       out = (float4*)d_out;

    int npatch  = in_sizes[0] / 64;                  // 393216
    int third   = npatch / 3;                        // 131072
    int nthread = third * 8;                         // 1048576
    int blocks  = (nthread + THREADS - 1) / THREADS; // 4096 (exact)

    dct15_kernel<<<blocks, THREADS>>>(in, out, third);
}